// round 8
// baseline (speedup 1.0000x reference)
#include <cuda_runtime.h>
#include <math.h>

// Problem constants: B=4, L=512, E=1024, H=128
#define LL 512
#define EE 1024
#define HH 128
#define NB 4

// Scratch (device globals: no allocation allowed)
// g_hid: [2*B*L][H] = rec_hid rows 0..2047, lig_hid rows 2048..4095
__device__ float g_hid[4096 * HH];
__device__ float g_part[256];   // per (batch, tile) partial max (4*32 used)

__device__ __forceinline__ float fast_tanh(float x) {
    float y;
    asm("tanh.approx.f32 %0, %1;" : "=f"(y) : "f"(x));
    return y;
}

// ---------------------------------------------------------------------------
// Kernel 1: hid = relu(X @ W1 + b1)   (M=4096, K=1024, N=128)
// BM=64, BN=64, BK=16, 512 threads, 2x4 micro-tile (4 warps/SMSP for
// latency hiding at the FFMA-issue bound). Double-buffered smem +
// register prefetch. As padded to stride 66 -> conflict-free transposed STS.
// ---------------------------------------------------------------------------
#define ASTR 66

__global__ __launch_bounds__(512) void gemm_hid_kernel(
    const float* __restrict__ rec, const float* __restrict__ lig,
    const float* __restrict__ W1, const float* __restrict__ b1)
{
    __shared__ __align__(16) float As[2][16][ASTR];
    __shared__ __align__(16) float Bs[2][16][64];
    const int bx = blockIdx.x;   // h tile: 0..1
    const int by = blockIdx.y;   // m tile: 0..63
    const int tid = threadIdx.x;
    const int tx = tid & 15;     // 4 cols
    const int ty = tid >> 4;     // 0..31, 2 rows

    // fill-role indices
    const int a_row = tid >> 3;          // 0..63
    const int a_e0  = (tid & 7) * 2;     // 0,2,..,14
    const int b_row = tid >> 5;          // 0..15
    const int b_h0  = (tid & 31) * 2;    // 0..62

    const int m_global = by * 64 + a_row;
    const float* src = (m_global < 2048)
        ? rec + (size_t)m_global * EE
        : lig + (size_t)(m_global - 2048) * EE;
    const float* wsrc = W1 + (size_t)b_row * HH + bx * 64 + b_h0;

    float c[2][4] = {};

    // prefetch tile 0
    float2 av = *(const float2*)(src + a_e0);
    float2 bv = *(const float2*)(wsrc);

    int buf = 0;
    for (int kk = 0; kk < 64; kk++) {
        // commit prefetched tile to smem[buf]
        As[buf][a_e0 + 0][a_row] = av.x;
        As[buf][a_e0 + 1][a_row] = av.y;
        *(float2*)&Bs[buf][b_row][b_h0] = bv;
        __syncthreads();

        // issue next tile's global loads; they complete during compute
        if (kk < 63) {
            av = *(const float2*)(src + (kk + 1) * 16 + a_e0);
            bv = *(const float2*)(wsrc + (size_t)(kk + 1) * 16 * HH);
        }

        #pragma unroll
        for (int k = 0; k < 16; k++) {
            float2 ar = *(const float2*)&As[buf][k][ty * 2];
            float4 br = *(const float4*)&Bs[buf][k][tx * 4];
            float aa[2] = {ar.x, ar.y};
            float bb[4] = {br.x, br.y, br.z, br.w};
            #pragma unroll
            for (int i = 0; i < 2; i++)
                #pragma unroll
                for (int j = 0; j < 4; j++)
                    c[i][j] += aa[i] * bb[j];
        }
        buf ^= 1;
        // WAR hazard on the other buffer is separated by the NEXT
        // iteration's __syncthreads (two-iteration distance) -> safe.
    }

    float4 bias = *(const float4*)(b1 + bx * 64 + tx * 4);
    float bb4[4] = {bias.x, bias.y, bias.z, bias.w};
    #pragma unroll
    for (int i = 0; i < 2; i++) {
        int m = by * 64 + ty * 2 + i;
        float4 o;
        o.x = fmaxf(c[i][0] + bb4[0], 0.f);
        o.y = fmaxf(c[i][1] + bb4[1], 0.f);
        o.z = fmaxf(c[i][2] + bb4[2], 0.f);
        o.w = fmaxf(c[i][3] + bb4[3], 0.f);
        *(float4*)&g_hid[(size_t)m * HH + bx * 64 + tx * 4] = o;
    }
}

// ---------------------------------------------------------------------------
// Kernel 2: fused tanh-outer-product + conv2x2 + max
// CTA tile: 32 (i) x 256 (j). 256 threads.
//   ty = tid>>5 (warp id): rows 4ty..4ty+3  -> r rows WARP-UNIFORM, so the
//        "r == 0 => whole tanh row is 0" ReLU skip is a uniform branch.
//   tx = tid&31: TWO 4-col groups at cols 4tx and 128+4tx.
//        float4 LDS at 16B/lane stride -> conflict-free (fixes R7's 8-way).
// Per-thread 4x(4+4) outputs via 5x(5+5) tanh halo. H chunked 4 x 32.
// ---------------------------------------------------------------------------
#define RST 36     // 33 halo rows padded
#define LST 260    // 257 halo cols padded (260*4 % 16 == 0 -> aligned float4)

__global__ __launch_bounds__(256) void bilinear_max_kernel(
    const float* __restrict__ convw)
{
    __shared__ __align__(16) float rs[32 * RST];   // [h][halo row]
    __shared__ __align__(16) float ls[32 * LST];   // [h][halo col]
    __shared__ __align__(16) float ws4[512];       // conv weights [h][2][2]
    __shared__ float red[256];

    const int b  = blockIdx.z;
    const int it = blockIdx.y;     // 0..15
    const int jt = blockIdx.x;     // 0..1
    const int tid = threadIdx.x;
    const int tx = tid & 31;
    const int ty = tid >> 5;       // warp id (warp-uniform rows)
    const int i0 = it * 32, j0 = jt * 256;

    const float* rhid = g_hid + (size_t)(b * LL) * HH;
    const float* lhid = g_hid + (size_t)(2048 + b * LL) * HH;

    for (int idx = tid; idx < 512; idx += 256) ws4[idx] = convw[idx];

    float accA[4][4] = {};
    float accB[4][4] = {};

    for (int hc = 0; hc < 4; hc++) {
        __syncthreads();   // previous chunk fully consumed (and ws4 on hc=0)
        // fill halo tiles (transposed [h][pos]); zero-pad left edges
        for (int idx = tid; idx < 33 * 32; idx += 256) {
            int row = idx >> 5, hh = idx & 31;
            int gi = i0 - 1 + row;
            rs[hh * RST + row] = (gi >= 0) ? rhid[(size_t)gi * HH + hc * 32 + hh] : 0.f;
        }
        for (int idx = tid; idx < 257 * 32; idx += 256) {
            int col = idx >> 5, hh = idx & 31;
            int gj = j0 - 1 + col;
            ls[hh * LST + col] = (gj >= 0) ? lhid[(size_t)gj * HH + hc * 32 + hh] : 0.f;
        }
        __syncthreads();

        #pragma unroll 1
        for (int hh = 0; hh < 32; hh++) {
            const float* rp = rs + hh * RST + 4 * ty;   // halo rows (uniform)
            const float* lp = ls + hh * LST + 4 * tx;
            float rr[5];
            #pragma unroll
            for (int r = 0; r < 5; r++) rr[r] = rp[r];  // warp-uniform bcast
            float4 a4 = *(const float4*)lp;       float a5 = lp[4];
            float4 b4 = *(const float4*)(lp + 128); float b5 = lp[132];
            float la[5] = {a4.x, a4.y, a4.z, a4.w, a5};
            float lb[5] = {b4.x, b4.y, b4.z, b4.w, b5};
            float4 w4 = *(const float4*)(ws4 + (hc * 32 + hh) * 4);

            #pragma unroll
            for (int u = 0; u < 5; u++) {
                float rv = rr[u];
                if (rv != 0.f) {            // warp-uniform branch (ReLU zeros)
                    float tA[5], tB[5];
                    #pragma unroll
                    for (int v = 0; v < 5; v++) {
                        tA[v] = fast_tanh(rv * la[v]);
                        tB[v] = fast_tanh(rv * lb[v]);
                    }
                    if (u < 4) {            // t row u as dp=0 for output row u
                        #pragma unroll
                        for (int q = 0; q < 4; q++) {
                            accA[u][q] += w4.x * tA[q] + w4.y * tA[q + 1];
                            accB[u][q] += w4.x * tB[q] + w4.y * tB[q + 1];
                        }
                    }
                    if (u > 0) {            // t row u as dp=1 for row u-1
                        #pragma unroll
                        for (int q = 0; q < 4; q++) {
                            accA[u - 1][q] += w4.z * tA[q] + w4.w * tA[q + 1];
                            accB[u - 1][q] += w4.z * tB[q] + w4.w * tB[q + 1];
                        }
                    }
                }
            }
        }
    }

    float m = accA[0][0];
    #pragma unroll
    for (int a = 0; a < 4; a++)
        #pragma unroll
        for (int q = 0; q < 4; q++) {
            m = fmaxf(m, accA[a][q]);
            m = fmaxf(m, accB[a][q]);
        }

    red[tid] = m;
    __syncthreads();
    #pragma unroll
    for (int s = 128; s > 0; s >>= 1) {
        if (tid < s) red[tid] = fmaxf(red[tid], red[tid + s]);
        __syncthreads();
    }
    if (tid == 0) g_part[b * 32 + it * 2 + jt] = red[0];
}

// ---------------------------------------------------------------------------
// Kernel 3: reduce 32 tile-maxes per batch, + conv_b, sigmoid
// ---------------------------------------------------------------------------
__global__ void finalize_kernel(const float* __restrict__ convb,
                                float* __restrict__ out)
{
    int w = threadIdx.x >> 5;     // warp id = batch
    int lane = threadIdx.x & 31;
    if (w < NB) {
        float m = g_part[w * 32 + lane];
        #pragma unroll
        for (int s = 16; s > 0; s >>= 1)
            m = fmaxf(m, __shfl_xor_sync(0xFFFFFFFFu, m, s));
        if (lane == 0) {
            float y = m + convb[0];
            out[w] = 1.f / (1.f + expf(-y));
        }
    }
}

extern "C" void kernel_launch(void* const* d_in, const int* in_sizes, int n_in,
                              void* d_out, int out_size)
{
    const float* rec   = (const float*)d_in[0];
    const float* lig   = (const float*)d_in[1];
    const float* W1    = (const float*)d_in[2];
    const float* b1    = (const float*)d_in[3];
    const float* convw = (const float*)d_in[4];
    const float* convb = (const float*)d_in[5];
    float* out = (float*)d_out;

    gemm_hid_kernel<<<dim3(2, 64), 512>>>(rec, lig, W1, b1);
    bilinear_max_kernel<<<dim3(2, 16, 4), 256>>>(convw);
    finalize_kernel<<<1, 128>>>(convb, out);
}

// round 11
// speedup vs baseline: 1.2537x; 1.2537x over previous
#include <cuda_runtime.h>
#include <math.h>

// Problem constants: B=4, L=512, E=1024, H=128
#define LL 512
#define EE 1024
#define HH 128
#define NB 4

// Scratch (device globals: no allocation allowed)
// g_hid: [2*B*L][H] = rec_hid rows 0..2047, lig_hid rows 2048..4095
__device__ float g_hid[4096 * HH];
__device__ float g_hpart[2 * 4096 * HH];  // split-K partial sums
__device__ float g_part[256];             // per (batch, tile) partial max

__device__ __forceinline__ float fast_tanh(float x) {
    float y;
    asm("tanh.approx.f32 %0, %1;" : "=f"(y) : "f"(x));
    return y;
}

// ---------------------------------------------------------------------------
// Kernel 1: split-K GEMM partials.  part[kz] = X @ W1[kz*512:(kz+1)*512]
// BM=64, BN=64, BK=16, 256 threads, 4x4 micro-tile (R7 shape — best so far).
// Double-buffered smem + register prefetch. grid (2, 64, 2) = 256 CTAs
// -> ~2 CTAs/SM, 4 warps/SMSP for latency hiding at the FFMA-issue bound.
// ---------------------------------------------------------------------------
__global__ __launch_bounds__(256) void gemm_hid_kernel(
    const float* __restrict__ rec, const float* __restrict__ lig,
    const float* __restrict__ W1)
{
    __shared__ __align__(16) float As[2][16][64];
    __shared__ __align__(16) float Bs[2][16][64];
    const int bx = blockIdx.x;   // h tile: 0..1
    const int by = blockIdx.y;   // m tile: 0..63
    const int bz = blockIdx.z;   // k half: 0..1
    const int tid = threadIdx.x;
    const int tx = tid & 15, ty = tid >> 4;

    // fill-role indices
    const int a_row = tid >> 2;          // 0..63
    const int a_e0  = (tid & 3) * 4;     // 0,4,8,12
    const int b_row = tid >> 4;          // 0..15
    const int b_h0  = (tid & 15) * 4;    // 0..60

    const int m_global = by * 64 + a_row;
    const float* src = ((m_global < 2048)
        ? rec + (size_t)m_global * EE
        : lig + (size_t)(m_global - 2048) * EE) + bz * 512;
    const float* wsrc = W1 + (size_t)(bz * 512 + b_row) * HH + bx * 64 + b_h0;

    float c[4][4] = {};

    // prefetch tile 0
    float4 av = *(const float4*)(src + a_e0);
    float4 bv = *(const float4*)(wsrc);

    int buf = 0;
    for (int kk = 0; kk < 32; kk++) {
        // commit prefetched tile to smem[buf]
        As[buf][a_e0 + 0][a_row] = av.x;
        As[buf][a_e0 + 1][a_row] = av.y;
        As[buf][a_e0 + 2][a_row] = av.z;
        As[buf][a_e0 + 3][a_row] = av.w;
        *(float4*)&Bs[buf][b_row][b_h0] = bv;
        __syncthreads();

        // issue next tile's global loads; they complete during compute
        if (kk < 31) {
            av = *(const float4*)(src + (kk + 1) * 16 + a_e0);
            bv = *(const float4*)(wsrc + (size_t)(kk + 1) * 16 * HH);
        }

        #pragma unroll
        for (int k = 0; k < 16; k++) {
            float4 ar = *(const float4*)&As[buf][k][ty * 4];
            float4 br = *(const float4*)&Bs[buf][k][tx * 4];
            float aa[4] = {ar.x, ar.y, ar.z, ar.w};
            float bb[4] = {br.x, br.y, br.z, br.w};
            #pragma unroll
            for (int i = 0; i < 4; i++)
                #pragma unroll
                for (int j = 0; j < 4; j++)
                    c[i][j] += aa[i] * bb[j];
        }
        buf ^= 1;
        // WAR hazard on the other buffer is two iterations away, separated
        // by the next iteration's __syncthreads -> safe.
    }

    float* dst = g_hpart + (size_t)bz * 4096 * HH;
    #pragma unroll
    for (int i = 0; i < 4; i++) {
        int m = by * 64 + ty * 4 + i;
        float4 o = {c[i][0], c[i][1], c[i][2], c[i][3]};
        *(float4*)&dst[(size_t)m * HH + bx * 64 + tx * 4] = o;
    }
}

// ---------------------------------------------------------------------------
// Kernel 1b: combine split-K halves + bias + ReLU -> g_hid
// 4096*128 = 524288 floats = 131072 float4.
// ---------------------------------------------------------------------------
__global__ __launch_bounds__(256) void combine_kernel(const float* __restrict__ b1)
{
    int i = blockIdx.x * 256 + threadIdx.x;      // float4 index
    const float4* p0 = (const float4*)g_hpart;
    const float4* p1 = (const float4*)(g_hpart + 4096 * HH);
    float4 a = p0[i], b = p1[i];
    float4 bias = *(const float4*)(b1 + (i & 31) * 4);
    float4 o;
    o.x = fmaxf(a.x + b.x + bias.x, 0.f);
    o.y = fmaxf(a.y + b.y + bias.y, 0.f);
    o.z = fmaxf(a.z + b.z + bias.z, 0.f);
    o.w = fmaxf(a.w + b.w + bias.w, 0.f);
    ((float4*)g_hid)[i] = o;
}

// ---------------------------------------------------------------------------
// Kernel 2: fused tanh-outer-product + conv2x2 + max
// CTA tile: 32 (i) x 128 (j). 256 threads, grid (4,16,4)=256 CTAs
// (~2 CTAs/SM -> 4 warps/SMSP hides MUFU + branch latency).
//   ty = tid>>5 (warp id): rows 4ty..4ty+3 -> r rows WARP-UNIFORM, so the
//        "r == 0 => whole tanh row is 0" ReLU skip is a uniform branch.
//   tx = tid&31: cols 4tx..4tx+3; float4 LDS at 16B/lane -> conflict-free.
// Per-thread 4x4 outputs via 5x5 tanh halo. H chunked 4 x 32.
// ---------------------------------------------------------------------------
#define RST 36     // 33 halo rows padded
#define LST 132    // 129 halo cols padded (132*4 % 16 == 0)

__global__ __launch_bounds__(256) void bilinear_max_kernel(
    const float* __restrict__ convw)
{
    __shared__ __align__(16) float rs[32 * RST];   // [h][halo row]
    __shared__ __align__(16) float ls[32 * LST];   // [h][halo col]
    __shared__ __align__(16) float ws4[512];       // conv weights [h][2][2]
    __shared__ float red[256];

    const int b  = blockIdx.z;
    const int it = blockIdx.y;     // 0..15
    const int jt = blockIdx.x;     // 0..3
    const int tid = threadIdx.x;
    const int tx = tid & 31;
    const int ty = tid >> 5;       // warp id (warp-uniform rows)
    const int i0 = it * 32, j0 = jt * 128;

    const float* rhid = g_hid + (size_t)(b * LL) * HH;
    const float* lhid = g_hid + (size_t)(2048 + b * LL) * HH;

    for (int idx = tid; idx < 512; idx += 256) ws4[idx] = convw[idx];

    float acc[4][4] = {};

    for (int hc = 0; hc < 4; hc++) {
        __syncthreads();   // previous chunk fully consumed (and ws4 on hc=0)
        // fill halo tiles (transposed [h][pos]); zero-pad left edges
        for (int idx = tid; idx < 33 * 32; idx += 256) {
            int row = idx >> 5, hh = idx & 31;
            int gi = i0 - 1 + row;
            rs[hh * RST + row] = (gi >= 0) ? rhid[(size_t)gi * HH + hc * 32 + hh] : 0.f;
        }
        for (int idx = tid; idx < 129 * 32; idx += 256) {
            int col = idx >> 5, hh = idx & 31;
            int gj = j0 - 1 + col;
            ls[hh * LST + col] = (gj >= 0) ? lhid[(size_t)gj * HH + hc * 32 + hh] : 0.f;
        }
        __syncthreads();

        #pragma unroll 1
        for (int hh = 0; hh < 32; hh++) {
            const float* rp = rs + hh * RST + 4 * ty;   // halo rows (uniform)
            const float* lp = ls + hh * LST + 4 * tx;
            float rr[5];
            #pragma unroll
            for (int r = 0; r < 5; r++) rr[r] = rp[r];  // warp-uniform bcast
            float4 a4 = *(const float4*)lp;  float a5 = lp[4];
            float la[5] = {a4.x, a4.y, a4.z, a4.w, a5};
            float4 w4 = *(const float4*)(ws4 + (hc * 32 + hh) * 4);

            #pragma unroll
            for (int u = 0; u < 5; u++) {
                float rv = rr[u];
                if (rv != 0.f) {            // warp-uniform branch (ReLU zeros)
                    float t[5];
                    #pragma unroll
                    for (int v = 0; v < 5; v++) t[v] = fast_tanh(rv * la[v]);
                    if (u < 4) {            // t row u as dp=0 for output row u
                        #pragma unroll
                        for (int q = 0; q < 4; q++)
                            acc[u][q] += w4.x * t[q] + w4.y * t[q + 1];
                    }
                    if (u > 0) {            // t row u as dp=1 for row u-1
                        #pragma unroll
                        for (int q = 0; q < 4; q++)
                            acc[u - 1][q] += w4.z * t[q] + w4.w * t[q + 1];
                    }
                }
            }
        }
    }

    float m = acc[0][0];
    #pragma unroll
    for (int a = 0; a < 4; a++)
        #pragma unroll
        for (int q = 0; q < 4; q++)
            m = fmaxf(m, acc[a][q]);

    red[tid] = m;
    __syncthreads();
    #pragma unroll
    for (int s = 128; s > 0; s >>= 1) {
        if (tid < s) red[tid] = fmaxf(red[tid], red[tid + s]);
        __syncthreads();
    }
    if (tid == 0) g_part[b * 64 + it * 4 + jt] = red[0];
}

// ---------------------------------------------------------------------------
// Kernel 3: reduce 64 tile-maxes per batch, + conv_b, sigmoid
// ---------------------------------------------------------------------------
__global__ void finalize_kernel(const float* __restrict__ convb,
                                float* __restrict__ out)
{
    int w = threadIdx.x >> 5;     // warp id = batch
    int lane = threadIdx.x & 31;
    if (w < NB) {
        float m = fmaxf(g_part[w * 64 + lane], g_part[w * 64 + 32 + lane]);
        #pragma unroll
        for (int s = 16; s > 0; s >>= 1)
            m = fmaxf(m, __shfl_xor_sync(0xFFFFFFFFu, m, s));
        if (lane == 0) {
            float y = m + convb[0];
            out[w] = 1.f / (1.f + expf(-y));
        }
    }
}

extern "C" void kernel_launch(void* const* d_in, const int* in_sizes, int n_in,
                              void* d_out, int out_size)
{
    const float* rec   = (const float*)d_in[0];
    const float* lig   = (const float*)d_in[1];
    const float* W1    = (const float*)d_in[2];
    const float* b1    = (const float*)d_in[3];
    const float* convw = (const float*)d_in[4];
    const float* convb = (const float*)d_in[5];
    float* out = (float*)d_out;

    gemm_hid_kernel<<<dim3(2, 64, 2), 256>>>(rec, lig, W1);
    combine_kernel<<<512, 256>>>(b1);
    bilinear_max_kernel<<<dim3(4, 16, 4), 256>>>(convw);
    finalize_kernel<<<1, 128>>>(convb, out);
}